// round 11
// baseline (speedup 1.0000x reference)
#include <cuda_runtime.h>
#include <cuda_bf16.h>
#include <cstdint>

#define N_NODES 50000
#define N_EDGES 800000
#define N_GRAPHS 256
#define DD 128
#define DV 32
#define NLAYERS 3
#define NBLK 3125                 // 16-row blocks (50000 = 3125*16 exactly)
#define GRID_GEMM 391             // ceil(3125/8)
#define BN_EPS 1e-5f

// ---- gemm kernel smem layout (bytes): W hi | W lo | bias | stats ----
#define WLO_OFF  32768
#define OFF_BS   65536
#define OFF_ST   66048
#define SMEM_G1  66048
#define SMEM_G2  67072

__device__ __forceinline__ uint32_t smem_u32(const void* p) {
    uint32_t a;
    asm("{ .reg .u64 t; cvta.to.shared.u64 t, %1; cvt.u32.u64 %0, t; }" : "=r"(a) : "l"(p));
    return a;
}
__device__ __forceinline__ uint32_t pack_bf16x2(float a, float b) {
    uint32_t r;
    asm("cvt.rn.bf16x2.f32 %0, %1, %2;" : "=r"(r) : "f"(b), "f"(a));
    return r;
}
__device__ __forceinline__ float bf_round(float v) {
    return __bfloat162float(__float2bfloat16(v));
}
__device__ __forceinline__ void ldsm_x4_t(uint32_t* r, uint32_t addr) {
    asm volatile("ldmatrix.sync.aligned.m8n8.x4.trans.shared.b16 {%0,%1,%2,%3}, [%4];"
                 : "=r"(r[0]), "=r"(r[1]), "=r"(r[2]), "=r"(r[3]) : "r"(addr));
}
__device__ __forceinline__ void mma16816(float* c, const uint32_t* a, uint32_t b0, uint32_t b1) {
    asm volatile(
        "mma.sync.aligned.m16n8k16.row.col.f32.bf16.bf16.f32 "
        "{%0,%1,%2,%3}, {%4,%5,%6,%7}, {%8,%9}, {%0,%1,%2,%3};"
        : "+f"(c[0]), "+f"(c[1]), "+f"(c[2]), "+f"(c[3])
        : "r"(a[0]), "r"(a[1]), "r"(a[2]), "r"(a[3]), "r"(b0), "r"(b1));
}

// ---------------- scratch ----------------
__device__ float4 g_xa[N_NODES * DV];
__device__ float4 g_xb[N_NODES * DV];
__device__ uint2  g_hhi[N_NODES * 32];      // H hi (bf16 row-major, 4 vals/lane)
__device__ uint2  g_hlo[N_NODES * 32];
__device__ uint4  g_thi[NBLK * 8 * 32];     // T hi in A-fragment layout [blk][ks][lane]
__device__ uint4  g_tlo[NBLK * 8 * 32];
__device__ int    g_deg[N_NODES];
__device__ int    g_off[N_NODES + 1];
__device__ int    g_cur[N_NODES];
__device__ int    g_csr[N_EDGES];
__device__ float  g_stats[NLAYERS * 2 * DD];
__device__ float4 g_pool[N_GRAPHS * DV];
__device__ float  g_cnt[N_GRAPHS];

// ---------------- CSR build ----------------
__global__ void k_deg(const int* __restrict__ ei) {
    int e = blockIdx.x * blockDim.x + threadIdx.x;
    if (e >= N_EDGES) return;
    unsigned d = (unsigned)ei[N_EDGES + e];
    if (d < N_NODES) atomicAdd(&g_deg[d], 1);
}
__global__ void k_scan() {
    __shared__ int sbuf[1024];
    __shared__ int carry;
    if (threadIdx.x == 0) carry = 0;
    __syncthreads();
    for (int base = 0; base < N_NODES; base += 1024) {
        int i = base + threadIdx.x;
        int v = (i < N_NODES) ? g_deg[i] : 0;
        sbuf[threadIdx.x] = v;
        __syncthreads();
        for (int ofs = 1; ofs < 1024; ofs <<= 1) {
            int tv = (threadIdx.x >= ofs) ? sbuf[threadIdx.x - ofs] : 0;
            __syncthreads();
            sbuf[threadIdx.x] += tv;
            __syncthreads();
        }
        if (i < N_NODES) g_off[i + 1] = carry + sbuf[threadIdx.x];
        __syncthreads();
        if (threadIdx.x == 0) carry += sbuf[1023];
        __syncthreads();
    }
    if (threadIdx.x == 0) g_off[0] = 0;
}
__global__ void k_fill(const int* __restrict__ ei) {
    int e = blockIdx.x * blockDim.x + threadIdx.x;
    if (e >= N_EDGES) return;
    unsigned s = (unsigned)ei[e];
    unsigned d = (unsigned)ei[N_EDGES + e];
    if (s >= N_NODES || d >= N_NODES) return;
    int pos = atomicAdd(&g_cur[d], 1);
    g_csr[g_off[d] + pos] = (int)s;
}

// ---------------- gather: CSR walk + GIN combine + BN fold -> H hi/lo ----------------
__global__ void __launch_bounds__(256) k_gather(
    const float4* __restrict__ in,
    const float* __restrict__ stats_in,
    const float* __restrict__ gm, const float* __restrict__ bt,
    const float* __restrict__ epsp)
{
    const int lane = threadIdx.x & 31;
    const int gwarp = (blockIdx.x * blockDim.x + threadIdx.x) >> 5;
    const int nwarps = (gridDim.x * blockDim.x) >> 5;
    const float eps1 = 1.0f + epsp[0];

    float4 sc4 = make_float4(1.f, 1.f, 1.f, 1.f);
    float4 sh4 = make_float4(0.f, 0.f, 0.f, 0.f);
    if (stats_in) {
        const float invN = 1.0f / (float)N_NODES;
        int f = lane * 4;
        float* scp = reinterpret_cast<float*>(&sc4);
        float* shp = reinterpret_cast<float*>(&sh4);
        #pragma unroll
        for (int i = 0; i < 4; i++) {
            float mu = stats_in[f + i] * invN;
            float var = fmaf(stats_in[DD + f + i], invN, -mu * mu);
            float sc = gm[f + i] * rsqrtf(var + BN_EPS);
            scp[i] = sc;
            shp[i] = bt[f + i] - mu * sc;
        }
    }

    for (int node = gwarp; node < N_NODES; node += nwarps) {
        int beg = g_off[node], end = g_off[node + 1];
        float4 xv = in[node * DV + lane];
        float4 acc = make_float4(0.f, 0.f, 0.f, 0.f);
        int e = beg;
        for (; e + 4 <= end; e += 4) {
            int j0 = g_csr[e], j1 = g_csr[e+1], j2 = g_csr[e+2], j3 = g_csr[e+3];
            float4 v0 = in[j0 * DV + lane];
            float4 v1 = in[j1 * DV + lane];
            float4 v2 = in[j2 * DV + lane];
            float4 v3 = in[j3 * DV + lane];
            acc.x += (v0.x + v1.x) + (v2.x + v3.x);
            acc.y += (v0.y + v1.y) + (v2.y + v3.y);
            acc.z += (v0.z + v1.z) + (v2.z + v3.z);
            acc.w += (v0.w + v1.w) + (v2.w + v3.w);
        }
        for (; e < end; e++) {
            float4 v0 = in[g_csr[e] * DV + lane];
            acc.x += v0.x; acc.y += v0.y; acc.z += v0.z; acc.w += v0.w;
        }
        float f = eps1 + (float)(end - beg);
        float h0 = fmaf(sc4.x, fmaf(eps1, xv.x, acc.x), f * sh4.x);
        float h1 = fmaf(sc4.y, fmaf(eps1, xv.y, acc.y), f * sh4.y);
        float h2 = fmaf(sc4.z, fmaf(eps1, xv.z, acc.z), f * sh4.z);
        float h3 = fmaf(sc4.w, fmaf(eps1, xv.w, acc.w), f * sh4.w);
        g_hhi[node * 32 + lane] = make_uint2(pack_bf16x2(h0, h1), pack_bf16x2(h2, h3));
        g_hlo[node * 32 + lane] = make_uint2(
            pack_bf16x2(h0 - bf_round(h0), h1 - bf_round(h1)),
            pack_bf16x2(h2 - bf_round(h2), h3 - bf_round(h3)));
    }
}

// ---- shared helper: stage one weight matrix hi/lo into XOR-swizzled K-major smem ----
__device__ __forceinline__ void stage_weights(char* sm, const float* __restrict__ W,
                                              const float* __restrict__ b, int t) {
    for (int i4 = t; i4 < DD * 32; i4 += 256) {
        int d = i4 >> 5, m = i4 & 31;
        float4 w = reinterpret_cast<const float4*>(W)[i4];
        uint32_t byte = (uint32_t)d * 256 + ((((uint32_t)(m >> 1)) ^ (d & 7)) << 4) + ((m & 1) << 3);
        *reinterpret_cast<uint2*>(sm + byte) =
            make_uint2(pack_bf16x2(w.x, w.y), pack_bf16x2(w.z, w.w));
        *reinterpret_cast<uint2*>(sm + WLO_OFF + byte) =
            make_uint2(pack_bf16x2(w.x - bf_round(w.x), w.y - bf_round(w.y)),
                       pack_bf16x2(w.z - bf_round(w.z), w.w - bf_round(w.w)));
    }
    if (t < DD) reinterpret_cast<float*>(sm)[OFF_BS / 4 + t] = b[t];
}

// ---- shared helper: bf16x3 chain, B from smem, A frags supplied per chunk ----
#define CHAIN_STEP(acc, ah, al, bBase, ks) do { \
    uint32_t bRow = (bBase) + (uint32_t)(16 * (ks) + kofs) * 256; \
    _Pragma("unroll") \
    for (int jp = 0; jp < 8; jp++) { \
        uint32_t bh[4], bl[4]; \
        uint32_t baddr = bRow + (uint32_t)(((2 * jp + nsel) ^ l7) << 4); \
        ldsm_x4_t(bh, baddr); \
        ldsm_x4_t(bl, baddr + WLO_OFF); \
        mma16816(acc[2*jp],   ah, bh[0], bh[1]); \
        mma16816(acc[2*jp+1], ah, bh[2], bh[3]); \
        mma16816(acc[2*jp],   al, bh[0], bh[1]); \
        mma16816(acc[2*jp+1], al, bh[2], bh[3]); \
        mma16816(acc[2*jp],   ah, bl[0], bl[1]); \
        mma16816(acc[2*jp+1], ah, bl[2], bl[3]); \
    } \
} while (0)

// ---------------- GEMM1: T-frags = relu(H @ W1 + b1), A from g_h*, out frag-layout ----
extern __shared__ char gsm[];
__global__ void __launch_bounds__(256, 2) k_gemm1(
    const float* __restrict__ W1, const float* __restrict__ b1)
{
    const uint32_t sb = smem_u32(gsm);
    float* smemf = reinterpret_cast<float*>(gsm);
    const int t = threadIdx.x;
    const int lane = t & 31, wid = t >> 5;

    stage_weights(gsm, W1, b1, t);
    __syncthreads();

    const int blk = blockIdx.x * 8 + wid;
    if (blk >= NBLK) return;

    const int g = lane >> 2, tt = lane & 3;
    const int sel = lane >> 3;
    const int kofs = (lane & 7) + (sel & 1) * 8;
    const int nsel = sel >> 1;
    const int l7 = lane & 7;

    const uint32_t* hh = reinterpret_cast<const uint32_t*>(g_hhi);
    const uint32_t* hl = reinterpret_cast<const uint32_t*>(g_hlo);
    const int r0 = (blk * 16 + g) * 64;       // uint32 row base (64 pairs/row)
    const int r1 = r0 + 8 * 64;

    float acc[16][4];
    #pragma unroll
    for (int j = 0; j < 16; j++) { acc[j][0]=0.f; acc[j][1]=0.f; acc[j][2]=0.f; acc[j][3]=0.f; }

    #pragma unroll 1
    for (int ks = 0; ks < 8; ks++) {
        int p = ks * 8 + tt;
        uint32_t ah[4], al[4];
        ah[0] = hh[r0 + p]; ah[1] = hh[r1 + p]; ah[2] = hh[r0 + p + 4]; ah[3] = hh[r1 + p + 4];
        al[0] = hl[r0 + p]; al[1] = hl[r1 + p]; al[2] = hl[r0 + p + 4]; al[3] = hl[r1 + p + 4];
        CHAIN_STEP(acc, ah, al, sb, ks);
    }

    // epilogue: bias + relu, emit T directly in A-fragment layout (hi/lo)
    #pragma unroll
    for (int ks = 0; ks < 8; ks++) {
        int j0 = 2 * ks, j1 = 2 * ks + 1;
        float b00 = smemf[OFF_BS/4 + 16*ks + 2*tt],     b01 = smemf[OFF_BS/4 + 16*ks + 2*tt + 1];
        float b10 = smemf[OFF_BS/4 + 16*ks + 8 + 2*tt], b11 = smemf[OFF_BS/4 + 16*ks + 8 + 2*tt + 1];
        float t0 = fmaxf(acc[j0][0] + b00, 0.f), t1 = fmaxf(acc[j0][1] + b01, 0.f);
        float t2 = fmaxf(acc[j0][2] + b00, 0.f), t3 = fmaxf(acc[j0][3] + b01, 0.f);
        float t4 = fmaxf(acc[j1][0] + b10, 0.f), t5 = fmaxf(acc[j1][1] + b11, 0.f);
        float t6 = fmaxf(acc[j1][2] + b10, 0.f), t7 = fmaxf(acc[j1][3] + b11, 0.f);
        uint4 hi, lo;
        hi.x = pack_bf16x2(t0, t1); hi.y = pack_bf16x2(t2, t3);
        hi.z = pack_bf16x2(t4, t5); hi.w = pack_bf16x2(t6, t7);
        lo.x = pack_bf16x2(t0 - bf_round(t0), t1 - bf_round(t1));
        lo.y = pack_bf16x2(t2 - bf_round(t2), t3 - bf_round(t3));
        lo.z = pack_bf16x2(t4 - bf_round(t4), t5 - bf_round(t5));
        lo.w = pack_bf16x2(t6 - bf_round(t6), t7 - bf_round(t7));
        int idx = (blk * 8 + ks) * 32 + lane;
        g_thi[idx] = hi;
        g_tlo[idx] = lo;
    }
}

// ---------------- GEMM2: y = relu(T @ W2 + b2), A = T-frags, + BN stats ----------------
__global__ void __launch_bounds__(256, 2) k_gemm2(
    float4* __restrict__ out,
    const float* __restrict__ W2, const float* __restrict__ b2,
    float* __restrict__ stats_out)
{
    const uint32_t sb = smem_u32(gsm);
    float* smemf = reinterpret_cast<float*>(gsm);
    const int t = threadIdx.x;
    const int lane = t & 31, wid = t >> 5;

    stage_weights(gsm, W2, b2, t);
    smemf[OFF_ST/4 + t] = 0.0f;
    __syncthreads();

    const int blk = blockIdx.x * 8 + wid;
    const bool active = blk < NBLK;
    const int g = lane >> 2, tt = lane & 3;
    const int sel = lane >> 3;
    const int kofs = (lane & 7) + (sel & 1) * 8;
    const int nsel = sel >> 1;
    const int l7 = lane & 7;

    if (active) {
        float acc[16][4];
        #pragma unroll
        for (int j = 0; j < 16; j++) { acc[j][0]=0.f; acc[j][1]=0.f; acc[j][2]=0.f; acc[j][3]=0.f; }

        #pragma unroll 1
        for (int ks = 0; ks < 8; ks++) {
            int idx = (blk * 8 + ks) * 32 + lane;
            uint4 hi = g_thi[idx];
            uint4 lo = g_tlo[idx];
            CHAIN_STEP(acc, reinterpret_cast<uint32_t*>(&hi), reinterpret_cast<uint32_t*>(&lo), sb, ks);
        }

        // epilogue: y = relu(acc + b2); store row-major; BN stats (smem-staged)
        int node0 = blk * 16 + g;
        int node1 = node0 + 8;
        float2* outv2 = reinterpret_cast<float2*>(out);
        #pragma unroll
        for (int j = 0; j < 16; j++) {
            int n0 = 8 * j + 2 * tt;
            float be0 = smemf[OFF_BS/4 + n0], be1 = smemf[OFF_BS/4 + n0 + 1];
            float y0 = fmaxf(acc[j][0] + be0, 0.f);
            float y1 = fmaxf(acc[j][1] + be1, 0.f);
            float y2 = fmaxf(acc[j][2] + be0, 0.f);
            float y3 = fmaxf(acc[j][3] + be1, 0.f);
            outv2[node0 * 64 + 4 * j + tt] = make_float2(y0, y1);
            outv2[node1 * 64 + 4 * j + tt] = make_float2(y2, y3);
            float se = y0 + y2, so = y1 + y3;
            float qe = y0*y0 + y2*y2, qo = y1*y1 + y3*y3;
            #pragma unroll
            for (int off = 4; off < 32; off <<= 1) {
                se += __shfl_xor_sync(0xFFFFFFFFu, se, off);
                so += __shfl_xor_sync(0xFFFFFFFFu, so, off);
                qe += __shfl_xor_sync(0xFFFFFFFFu, qe, off);
                qo += __shfl_xor_sync(0xFFFFFFFFu, qo, off);
            }
            if (g == 0) {
                atomicAdd(&smemf[OFF_ST/4 + n0],           se);
                atomicAdd(&smemf[OFF_ST/4 + n0 + 1],       so);
                atomicAdd(&smemf[OFF_ST/4 + 128 + n0],     qe);
                atomicAdd(&smemf[OFF_ST/4 + 128 + n0 + 1], qo);
            }
        }
    }

    __syncthreads();
    atomicAdd(&stats_out[t], smemf[OFF_ST/4 + t]);
}

// ---------------- pool + head ----------------
__global__ void k_pool(const int* __restrict__ batch, const float4* __restrict__ in) {
    int idx = blockIdx.x * blockDim.x + threadIdx.x;
    int n = idx >> 5;
    int k = idx & 31;
    if (n >= N_NODES) return;
    unsigned g = (unsigned)batch[n];
    if (g >= N_GRAPHS) return;
    float4 v = in[n * DV + k];
    atomicAdd(&g_pool[g * DV + k], v);
    if (k == 0) atomicAdd(&g_cnt[g], 1.0f);
}

__global__ void k_final(const float* __restrict__ We, const float* __restrict__ be,
                        const float* __restrict__ gm, const float* __restrict__ bt,
                        float* __restrict__ out) {
    __shared__ float sp[DD];
    int b = blockIdx.x;
    int o = threadIdx.x;
    const float invN = 1.0f / (float)N_NODES;
    const float* st = g_stats + (NLAYERS - 1) * 2 * DD;
    float mu = st[o] * invN;
    float var = fmaf(st[DD + o], invN, -mu * mu);
    float sc = gm[o] * rsqrtf(var + BN_EPS);
    float sh = bt[o] - mu * sc;
    float c = fmaxf(g_cnt[b], 1.0f);
    float sum = reinterpret_cast<const float*>(g_pool)[b * DD + o];
    sp[o] = fmaf(sc, sum / c, sh);
    __syncthreads();
    float accv = be[o];
    #pragma unroll 4
    for (int d = 0; d < DD; d++) accv = fmaf(sp[d], We[d * DD + o], accv);
    out[b * DD + o] = accv;
}

extern "C" void kernel_launch(void* const* d_in, const int* in_sizes, int n_in,
                              void* d_out, int out_size) {
    const float* x     = (const float*)d_in[0];
    const int*   ei    = (const int*)d_in[1];
    const int*   batch = (const int*)d_in[2];
    const float* W1    = (const float*)d_in[3];
    const float* b1    = (const float*)d_in[4];
    const float* W2    = (const float*)d_in[5];
    const float* b2    = (const float*)d_in[6];
    const float* eps   = (const float*)d_in[7];
    const float* gamma = (const float*)d_in[8];
    const float* beta  = (const float*)d_in[9];
    const float* We    = (const float*)d_in[10];
    const float* be    = (const float*)d_in[11];
    float* out = (float*)d_out;

    void *p_xa, *p_xb, *p_deg, *p_cur, *p_stats, *p_pool, *p_cnt;
    cudaGetSymbolAddress(&p_xa, g_xa);
    cudaGetSymbolAddress(&p_xb, g_xb);
    cudaGetSymbolAddress(&p_deg, g_deg);
    cudaGetSymbolAddress(&p_cur, g_cur);
    cudaGetSymbolAddress(&p_stats, g_stats);
    cudaGetSymbolAddress(&p_pool, g_pool);
    cudaGetSymbolAddress(&p_cnt, g_cnt);
    float* stats = (float*)p_stats;

    cudaFuncSetAttribute(k_gemm1, cudaFuncAttributeMaxDynamicSharedMemorySize, SMEM_G1);
    cudaFuncSetAttribute(k_gemm2, cudaFuncAttributeMaxDynamicSharedMemorySize, SMEM_G2);

    cudaMemsetAsync(p_deg, 0, N_NODES * sizeof(int), 0);
    cudaMemsetAsync(p_cur, 0, N_NODES * sizeof(int), 0);
    cudaMemsetAsync(p_stats, 0, NLAYERS * 2 * DD * sizeof(float), 0);
    const int eb = (N_EDGES + 255) / 256;
    k_deg<<<eb, 256>>>(ei);
    k_scan<<<1, 1024>>>();
    k_fill<<<eb, 256>>>(ei);

    const float4* bufs_in[3]  = { (const float4*)x, (const float4*)p_xa, (const float4*)p_xb };
    float4*       bufs_out[3] = { (float4*)p_xa, (float4*)p_xb, (float4*)p_xa };
    for (int l = 0; l < NLAYERS; l++) {
        const float* st_in = (l == 0) ? nullptr : stats + (l - 1) * 2 * DD;
        const float* gm = (l == 0) ? gamma : gamma + (l - 1) * DD;
        const float* bt = (l == 0) ? beta  : beta  + (l - 1) * DD;
        k_gather<<<1184, 256>>>(bufs_in[l], st_in, gm, bt, eps + l);
        k_gemm1<<<GRID_GEMM, 256, SMEM_G1>>>(W1 + l*DD*DD, b1 + l*DD);
        k_gemm2<<<GRID_GEMM, 256, SMEM_G2>>>(bufs_out[l], W2 + l*DD*DD, b2 + l*DD,
                                             stats + l * 2 * DD);
    }

    cudaMemsetAsync(p_pool, 0, (size_t)N_GRAPHS * DD * sizeof(float), 0);
    cudaMemsetAsync(p_cnt, 0, N_GRAPHS * sizeof(float), 0);
    const int pool_blocks = (N_NODES * 32 + 255) / 256;
    k_pool<<<pool_blocks, 256>>>(batch, bufs_out[NLAYERS - 1]);
    k_final<<<N_GRAPHS, DD>>>(We, be, gamma + (NLAYERS-1)*DD, beta + (NLAYERS-1)*DD, out);
}

// round 12
// speedup vs baseline: 1.1067x; 1.1067x over previous
#include <cuda_runtime.h>
#include <cuda_bf16.h>
#include <cstdint>

#define N_NODES 50000
#define N_EDGES 800000
#define N_GRAPHS 256
#define DD 128
#define DV 32
#define NLAYERS 3
#define NBLK 3125                 // 16-row blocks (50000 = 3125*16 exactly)
#define GRID_GEMM 148
#define BN_EPS 1e-5f

// ---- k_gemm smem layout (bytes): W1 hi|lo, W2 hi|lo, b1, b2, stats ----
#define WLO_OFF  32768
#define OFF_W1   0
#define OFF_W2   65536
#define OFF_BS1  131072
#define OFF_BS2  131584
#define OFF_ST   132096
#define SMEM_G   133120

__device__ __forceinline__ uint32_t smem_u32(const void* p) {
    uint32_t a;
    asm("{ .reg .u64 t; cvta.to.shared.u64 t, %1; cvt.u32.u64 %0, t; }" : "=r"(a) : "l"(p));
    return a;
}
__device__ __forceinline__ uint32_t pack_bf16x2(float a, float b) {
    uint32_t r;
    asm("cvt.rn.bf16x2.f32 %0, %1, %2;" : "=r"(r) : "f"(b), "f"(a));
    return r;
}
__device__ __forceinline__ float bf_round(float v) {
    return __bfloat162float(__float2bfloat16(v));
}
__device__ __forceinline__ void ldsm_x4_t(uint32_t* r, uint32_t addr) {
    asm volatile("ldmatrix.sync.aligned.m8n8.x4.trans.shared.b16 {%0,%1,%2,%3}, [%4];"
                 : "=r"(r[0]), "=r"(r[1]), "=r"(r[2]), "=r"(r[3]) : "r"(addr));
}
__device__ __forceinline__ void mma16816(float* c, const uint32_t* a, uint32_t b0, uint32_t b1) {
    asm volatile(
        "mma.sync.aligned.m16n8k16.row.col.f32.bf16.bf16.f32 "
        "{%0,%1,%2,%3}, {%4,%5,%6,%7}, {%8,%9}, {%0,%1,%2,%3};"
        : "+f"(c[0]), "+f"(c[1]), "+f"(c[2]), "+f"(c[3])
        : "r"(a[0]), "r"(a[1]), "r"(a[2]), "r"(a[3]), "r"(b0), "r"(b1));
}

// bf16x3 chain step: B from smem (lo at +WLO_OFF), A frags in registers
#define CHAIN_STEP(acc, ah, al, bBase, ks) do { \
    uint32_t bRow = (bBase) + (uint32_t)(16 * (ks) + kofs) * 256; \
    _Pragma("unroll") \
    for (int jp = 0; jp < 8; jp++) { \
        uint32_t bh[4], bl[4]; \
        uint32_t baddr = bRow + (uint32_t)(((2 * jp + nsel) ^ l7) << 4); \
        ldsm_x4_t(bh, baddr); \
        ldsm_x4_t(bl, baddr + WLO_OFF); \
        mma16816(acc[2*jp],   ah, bh[0], bh[1]); \
        mma16816(acc[2*jp+1], ah, bh[2], bh[3]); \
        mma16816(acc[2*jp],   al, bh[0], bh[1]); \
        mma16816(acc[2*jp+1], al, bh[2], bh[3]); \
        mma16816(acc[2*jp],   ah, bl[0], bl[1]); \
        mma16816(acc[2*jp+1], ah, bl[2], bl[3]); \
    } \
} while (0)

// ---------------- scratch ----------------
__device__ float4 g_xa[N_NODES * DV];
__device__ float4 g_xb[N_NODES * DV];
__device__ uint2  g_hhi[N_NODES * 32];      // H hi (bf16 row-major, 4 vals/lane)
__device__ uint2  g_hlo[N_NODES * 32];
__device__ int    g_deg[N_NODES];
__device__ int    g_off[N_NODES + 1];
__device__ int    g_cur[N_NODES];
__device__ int    g_csr[N_EDGES];
__device__ float  g_stats[NLAYERS * 2 * DD];
__device__ float4 g_pool[N_GRAPHS * DV];
__device__ float  g_cnt[N_GRAPHS];

// ---------------- CSR build ----------------
__global__ void k_deg(const int* __restrict__ ei) {
    int e = blockIdx.x * blockDim.x + threadIdx.x;
    if (e >= N_EDGES) return;
    unsigned d = (unsigned)ei[N_EDGES + e];
    if (d < N_NODES) atomicAdd(&g_deg[d], 1);
}
__global__ void k_scan() {
    __shared__ int sbuf[1024];
    __shared__ int carry;
    if (threadIdx.x == 0) carry = 0;
    __syncthreads();
    for (int base = 0; base < N_NODES; base += 1024) {
        int i = base + threadIdx.x;
        int v = (i < N_NODES) ? g_deg[i] : 0;
        sbuf[threadIdx.x] = v;
        __syncthreads();
        for (int ofs = 1; ofs < 1024; ofs <<= 1) {
            int tv = (threadIdx.x >= ofs) ? sbuf[threadIdx.x - ofs] : 0;
            __syncthreads();
            sbuf[threadIdx.x] += tv;
            __syncthreads();
        }
        if (i < N_NODES) g_off[i + 1] = carry + sbuf[threadIdx.x];
        __syncthreads();
        if (threadIdx.x == 0) carry += sbuf[1023];
        __syncthreads();
    }
    if (threadIdx.x == 0) g_off[0] = 0;
}
__global__ void k_fill(const int* __restrict__ ei) {
    int e = blockIdx.x * blockDim.x + threadIdx.x;
    if (e >= N_EDGES) return;
    unsigned s = (unsigned)ei[e];
    unsigned d = (unsigned)ei[N_EDGES + e];
    if (s >= N_NODES || d >= N_NODES) return;
    int pos = atomicAdd(&g_cur[d], 1);
    g_csr[g_off[d] + pos] = (int)s;
}

// ---------------- gather: CSR walk + GIN combine + BN fold -> H hi/lo ----------------
__global__ void __launch_bounds__(256) k_gather(
    const float4* __restrict__ in,
    const float* __restrict__ stats_in,
    const float* __restrict__ gm, const float* __restrict__ bt,
    const float* __restrict__ epsp)
{
    const int lane = threadIdx.x & 31;
    const int gwarp = (blockIdx.x * blockDim.x + threadIdx.x) >> 5;
    const int nwarps = (gridDim.x * blockDim.x) >> 5;
    const float eps1 = 1.0f + epsp[0];

    float4 sc4 = make_float4(1.f, 1.f, 1.f, 1.f);
    float4 sh4 = make_float4(0.f, 0.f, 0.f, 0.f);
    if (stats_in) {
        const float invN = 1.0f / (float)N_NODES;
        int f = lane * 4;
        float* scp = reinterpret_cast<float*>(&sc4);
        float* shp = reinterpret_cast<float*>(&sh4);
        #pragma unroll
        for (int i = 0; i < 4; i++) {
            float mu = stats_in[f + i] * invN;
            float var = fmaf(stats_in[DD + f + i], invN, -mu * mu);
            float sc = gm[f + i] * rsqrtf(var + BN_EPS);
            scp[i] = sc;
            shp[i] = bt[f + i] - mu * sc;
        }
    }

    for (int node = gwarp; node < N_NODES; node += nwarps) {
        int beg = g_off[node], end = g_off[node + 1];
        float4 xv = in[node * DV + lane];
        float4 acc = make_float4(0.f, 0.f, 0.f, 0.f);
        int e = beg;
        for (; e + 4 <= end; e += 4) {
            int j0 = g_csr[e], j1 = g_csr[e+1], j2 = g_csr[e+2], j3 = g_csr[e+3];
            float4 v0 = in[j0 * DV + lane];
            float4 v1 = in[j1 * DV + lane];
            float4 v2 = in[j2 * DV + lane];
            float4 v3 = in[j3 * DV + lane];
            acc.x += (v0.x + v1.x) + (v2.x + v3.x);
            acc.y += (v0.y + v1.y) + (v2.y + v3.y);
            acc.z += (v0.z + v1.z) + (v2.z + v3.z);
            acc.w += (v0.w + v1.w) + (v2.w + v3.w);
        }
        for (; e < end; e++) {
            float4 v0 = in[g_csr[e] * DV + lane];
            acc.x += v0.x; acc.y += v0.y; acc.z += v0.z; acc.w += v0.w;
        }
        float f = eps1 + (float)(end - beg);
        float h0 = fmaf(sc4.x, fmaf(eps1, xv.x, acc.x), f * sh4.x);
        float h1 = fmaf(sc4.y, fmaf(eps1, xv.y, acc.y), f * sh4.y);
        float h2 = fmaf(sc4.z, fmaf(eps1, xv.z, acc.z), f * sh4.z);
        float h3 = fmaf(sc4.w, fmaf(eps1, xv.w, acc.w), f * sh4.w);
        g_hhi[node * 32 + lane] = make_uint2(pack_bf16x2(h0, h1), pack_bf16x2(h2, h3));
        g_hlo[node * 32 + lane] = make_uint2(
            pack_bf16x2(h0 - bf_round(h0), h1 - bf_round(h1)),
            pack_bf16x2(h2 - bf_round(h2), h3 - bf_round(h3)));
    }
}

// ---------------- fused GEMM: y = relu(relu(H@W1+b1)@W2+b2), T register-resident ----
extern __shared__ char gsm[];
__global__ void __launch_bounds__(256, 1) k_gemm(
    float4* __restrict__ out,
    const float* __restrict__ W1, const float* __restrict__ b1,
    const float* __restrict__ W2, const float* __restrict__ b2,
    float* __restrict__ stats_out)
{
    const uint32_t sb = smem_u32(gsm);
    float* smemf = reinterpret_cast<float*>(gsm);
    const int t = threadIdx.x;
    const int lane = t & 31, wid = t >> 5;

    // stage W1 and W2 (hi/lo) into XOR-swizzled K-major smem
    for (int i4 = t; i4 < DD * 32; i4 += 256) {
        int d = i4 >> 5, m = i4 & 31;
        float4 w1 = reinterpret_cast<const float4*>(W1)[i4];
        float4 w2 = reinterpret_cast<const float4*>(W2)[i4];
        uint32_t byte = (uint32_t)d * 256 + ((((uint32_t)(m >> 1)) ^ (d & 7)) << 4) + ((m & 1) << 3);
        *reinterpret_cast<uint2*>(gsm + OFF_W1 + byte) =
            make_uint2(pack_bf16x2(w1.x, w1.y), pack_bf16x2(w1.z, w1.w));
        *reinterpret_cast<uint2*>(gsm + OFF_W1 + WLO_OFF + byte) =
            make_uint2(pack_bf16x2(w1.x - bf_round(w1.x), w1.y - bf_round(w1.y)),
                       pack_bf16x2(w1.z - bf_round(w1.z), w1.w - bf_round(w1.w)));
        *reinterpret_cast<uint2*>(gsm + OFF_W2 + byte) =
            make_uint2(pack_bf16x2(w2.x, w2.y), pack_bf16x2(w2.z, w2.w));
        *reinterpret_cast<uint2*>(gsm + OFF_W2 + WLO_OFF + byte) =
            make_uint2(pack_bf16x2(w2.x - bf_round(w2.x), w2.y - bf_round(w2.y)),
                       pack_bf16x2(w2.z - bf_round(w2.z), w2.w - bf_round(w2.w)));
    }
    if (t < DD) { smemf[OFF_BS1/4 + t] = b1[t]; smemf[OFF_BS2/4 + t] = b2[t]; }
    smemf[OFF_ST/4 + t] = 0.0f;
    __syncthreads();

    const int g = lane >> 2, tt = lane & 3;
    const int sel = lane >> 3;
    const int kofs = (lane & 7) + (sel & 1) * 8;
    const int nsel = sel >> 1;
    const int l7 = lane & 7;

    const uint32_t* hh = reinterpret_cast<const uint32_t*>(g_hhi);
    const uint32_t* hl = reinterpret_cast<const uint32_t*>(g_hlo);

    for (int blk = blockIdx.x * 8 + wid; blk < NBLK; blk += GRID_GEMM * 8) {
        const int r0 = (blk * 16 + g) * 64;
        const int r1 = r0 + 8 * 64;

        // load all A fragments of H (hi/lo), high MLP
        uint32_t ah[32], al[32];
        #pragma unroll
        for (int ks = 0; ks < 8; ks++) {
            int p = ks * 8 + tt;
            ah[4*ks+0] = hh[r0 + p];     ah[4*ks+1] = hh[r1 + p];
            ah[4*ks+2] = hh[r0 + p + 4]; ah[4*ks+3] = hh[r1 + p + 4];
            al[4*ks+0] = hl[r0 + p];     al[4*ks+1] = hl[r1 + p];
            al[4*ks+2] = hl[r0 + p + 4]; al[4*ks+3] = hl[r1 + p + 4];
        }

        // GEMM1
        float acc[16][4];
        #pragma unroll
        for (int j = 0; j < 16; j++) { acc[j][0]=0.f; acc[j][1]=0.f; acc[j][2]=0.f; acc[j][3]=0.f; }
        #pragma unroll
        for (int ks = 0; ks < 8; ks++)
            CHAIN_STEP(acc, &ah[4*ks], &al[4*ks], sb + OFF_W1, ks);

        // bias + relu + hi/lo split -> T fragments (overwrite ah/al in registers)
        #pragma unroll
        for (int ks = 0; ks < 8; ks++) {
            int j0 = 2 * ks, j1 = 2 * ks + 1;
            float b00 = smemf[OFF_BS1/4 + 16*ks + 2*tt],     b01 = smemf[OFF_BS1/4 + 16*ks + 2*tt + 1];
            float b10 = smemf[OFF_BS1/4 + 16*ks + 8 + 2*tt], b11 = smemf[OFF_BS1/4 + 16*ks + 8 + 2*tt + 1];
            float t0 = fmaxf(acc[j0][0] + b00, 0.f), t1 = fmaxf(acc[j0][1] + b01, 0.f);
            float t2 = fmaxf(acc[j0][2] + b00, 0.f), t3 = fmaxf(acc[j0][3] + b01, 0.f);
            float t4 = fmaxf(acc[j1][0] + b10, 0.f), t5 = fmaxf(acc[j1][1] + b11, 0.f);
            float t6 = fmaxf(acc[j1][2] + b10, 0.f), t7 = fmaxf(acc[j1][3] + b11, 0.f);
            ah[4*ks+0] = pack_bf16x2(t0, t1);
            ah[4*ks+1] = pack_bf16x2(t2, t3);
            ah[4*ks+2] = pack_bf16x2(t4, t5);
            ah[4*ks+3] = pack_bf16x2(t6, t7);
            al[4*ks+0] = pack_bf16x2(t0 - bf_round(t0), t1 - bf_round(t1));
            al[4*ks+1] = pack_bf16x2(t2 - bf_round(t2), t3 - bf_round(t3));
            al[4*ks+2] = pack_bf16x2(t4 - bf_round(t4), t5 - bf_round(t5));
            al[4*ks+3] = pack_bf16x2(t6 - bf_round(t6), t7 - bf_round(t7));
        }

        // GEMM2
        #pragma unroll
        for (int j = 0; j < 16; j++) { acc[j][0]=0.f; acc[j][1]=0.f; acc[j][2]=0.f; acc[j][3]=0.f; }
        #pragma unroll
        for (int ks = 0; ks < 8; ks++)
            CHAIN_STEP(acc, &ah[4*ks], &al[4*ks], sb + OFF_W2, ks);

        // epilogue: y = relu(acc + b2); store row-major; BN stats (smem-staged)
        {
            int node0 = blk * 16 + g;
            int node1 = node0 + 8;
            float2* outv2 = reinterpret_cast<float2*>(out);
            #pragma unroll
            for (int j = 0; j < 16; j++) {
                int n0 = 8 * j + 2 * tt;
                float be0 = smemf[OFF_BS2/4 + n0], be1 = smemf[OFF_BS2/4 + n0 + 1];
                float y0 = fmaxf(acc[j][0] + be0, 0.f);
                float y1 = fmaxf(acc[j][1] + be1, 0.f);
                float y2 = fmaxf(acc[j][2] + be0, 0.f);
                float y3 = fmaxf(acc[j][3] + be1, 0.f);
                outv2[node0 * 64 + 4 * j + tt] = make_float2(y0, y1);
                outv2[node1 * 64 + 4 * j + tt] = make_float2(y2, y3);
                float se = y0 + y2, so = y1 + y3;
                float qe = y0*y0 + y2*y2, qo = y1*y1 + y3*y3;
                #pragma unroll
                for (int off = 4; off < 32; off <<= 1) {
                    se += __shfl_xor_sync(0xFFFFFFFFu, se, off);
                    so += __shfl_xor_sync(0xFFFFFFFFu, so, off);
                    qe += __shfl_xor_sync(0xFFFFFFFFu, qe, off);
                    qo += __shfl_xor_sync(0xFFFFFFFFu, qo, off);
                }
                if (g == 0) {
                    atomicAdd(&smemf[OFF_ST/4 + n0],           se);
                    atomicAdd(&smemf[OFF_ST/4 + n0 + 1],       so);
                    atomicAdd(&smemf[OFF_ST/4 + 128 + n0],     qe);
                    atomicAdd(&smemf[OFF_ST/4 + 128 + n0 + 1], qo);
                }
            }
        }
    }

    __syncthreads();
    atomicAdd(&stats_out[t], smemf[OFF_ST/4 + t]);
}

// ---------------- pool + head ----------------
__global__ void k_pool(const int* __restrict__ batch, const float4* __restrict__ in) {
    int idx = blockIdx.x * blockDim.x + threadIdx.x;
    int n = idx >> 5;
    int k = idx & 31;
    if (n >= N_NODES) return;
    unsigned g = (unsigned)batch[n];
    if (g >= N_GRAPHS) return;
    float4 v = in[n * DV + k];
    atomicAdd(&g_pool[g * DV + k], v);
    if (k == 0) atomicAdd(&g_cnt[g], 1.0f);
}

__global__ void k_final(const float* __restrict__ We, const float* __restrict__ be,
                        const float* __restrict__ gm, const float* __restrict__ bt,
                        float* __restrict__ out) {
    __shared__ float sp[DD];
    int b = blockIdx.x;
    int o = threadIdx.x;
    const float invN = 1.0f / (float)N_NODES;
    const float* st = g_stats + (NLAYERS - 1) * 2 * DD;
    float mu = st[o] * invN;
    float var = fmaf(st[DD + o], invN, -mu * mu);
    float sc = gm[o] * rsqrtf(var + BN_EPS);
    float sh = bt[o] - mu * sc;
    float c = fmaxf(g_cnt[b], 1.0f);
    float sum = reinterpret_cast<const float*>(g_pool)[b * DD + o];
    sp[o] = fmaf(sc, sum / c, sh);
    __syncthreads();
    float accv = be[o];
    #pragma unroll 4
    for (int d = 0; d < DD; d++) accv = fmaf(sp[d], We[d * DD + o], accv);
    out[b * DD + o] = accv;
}

extern "C" void kernel_launch(void* const* d_in, const int* in_sizes, int n_in,
                              void* d_out, int out_size) {
    const float* x     = (const float*)d_in[0];
    const int*   ei    = (const int*)d_in[1];
    const int*   batch = (const int*)d_in[2];
    const float* W1    = (const float*)d_in[3];
    const float* b1    = (const float*)d_in[4];
    const float* W2    = (const float*)d_in[5];
    const float* b2    = (const float*)d_in[6];
    const float* eps   = (const float*)d_in[7];
    const float* gamma = (const float*)d_in[8];
    const float* beta  = (const float*)d_in[9];
    const float* We    = (const float*)d_in[10];
    const float* be    = (const float*)d_in[11];
    float* out = (float*)d_out;

    void *p_xa, *p_xb, *p_deg, *p_cur, *p_stats, *p_pool, *p_cnt;
    cudaGetSymbolAddress(&p_xa, g_xa);
    cudaGetSymbolAddress(&p_xb, g_xb);
    cudaGetSymbolAddress(&p_deg, g_deg);
    cudaGetSymbolAddress(&p_cur, g_cur);
    cudaGetSymbolAddress(&p_stats, g_stats);
    cudaGetSymbolAddress(&p_pool, g_pool);
    cudaGetSymbolAddress(&p_cnt, g_cnt);
    float* stats = (float*)p_stats;

    cudaFuncSetAttribute(k_gemm, cudaFuncAttributeMaxDynamicSharedMemorySize, SMEM_G);

    cudaMemsetAsync(p_deg, 0, N_NODES * sizeof(int), 0);
    cudaMemsetAsync(p_cur, 0, N_NODES * sizeof(int), 0);
    cudaMemsetAsync(p_stats, 0, NLAYERS * 2 * DD * sizeof(float), 0);
    const int eb = (N_EDGES + 255) / 256;
    k_deg<<<eb, 256>>>(ei);
    k_scan<<<1, 1024>>>();
    k_fill<<<eb, 256>>>(ei);

    const float4* bufs_in[3]  = { (const float4*)x, (const float4*)p_xa, (const float4*)p_xb };
    float4*       bufs_out[3] = { (float4*)p_xa, (float4*)p_xb, (float4*)p_xa };
    for (int l = 0; l < NLAYERS; l++) {
        const float* st_in = (l == 0) ? nullptr : stats + (l - 1) * 2 * DD;
        const float* gm = (l == 0) ? gamma : gamma + (l - 1) * DD;
        const float* bt = (l == 0) ? beta  : beta  + (l - 1) * DD;
        k_gather<<<1184, 256>>>(bufs_in[l], st_in, gm, bt, eps + l);
        k_gemm<<<GRID_GEMM, 256, SMEM_G>>>(bufs_out[l],
                                           W1 + l*DD*DD, b1 + l*DD,
                                           W2 + l*DD*DD, b2 + l*DD,
                                           stats + l * 2 * DD);
    }

    cudaMemsetAsync(p_pool, 0, (size_t)N_GRAPHS * DD * sizeof(float), 0);
    cudaMemsetAsync(p_cnt, 0, N_GRAPHS * sizeof(float), 0);
    const int pool_blocks = (N_NODES * 32 + 255) / 256;
    k_pool<<<pool_blocks, 256>>>(batch, bufs_out[NLAYERS - 1]);
    k_final<<<N_GRAPHS, DD>>>(We, be, gamma + (NLAYERS-1)*DD, beta + (NLAYERS-1)*DD, out);
}

// round 13
// speedup vs baseline: 1.3885x; 1.2546x over previous
#include <cuda_runtime.h>
#include <cuda_bf16.h>
#include <cstdint>

#define N_NODES 50000
#define N_EDGES 800000
#define N_GRAPHS 256
#define DD 128
#define DV 32
#define NLAYERS 3
#define NBLK 3125                 // 16-row blocks (50000 = 3125*16 exactly)
#define GRID_GEMM 148
#define GWARPS 12                 // warps per gemm CTA
#define BN_EPS 1e-5f
#define NSCAN 49                  // ceil(50000/1024)

// ---- k_gemm smem layout (bytes): W1 hi|lo, W2 hi|lo, b1, b2, stats ----
#define WLO_OFF  32768
#define OFF_W1   0
#define OFF_W2   65536
#define OFF_BS1  131072
#define OFF_BS2  131584
#define OFF_ST   132096
#define SMEM_G   133120

__device__ __forceinline__ uint32_t smem_u32(const void* p) {
    uint32_t a;
    asm("{ .reg .u64 t; cvta.to.shared.u64 t, %1; cvt.u32.u64 %0, t; }" : "=r"(a) : "l"(p));
    return a;
}
__device__ __forceinline__ uint32_t pack_bf16x2(float a, float b) {
    uint32_t r;
    asm("cvt.rn.bf16x2.f32 %0, %1, %2;" : "=r"(r) : "f"(b), "f"(a));
    return r;
}
__device__ __forceinline__ float bf_round(float v) {
    return __bfloat162float(__float2bfloat16(v));
}
__device__ __forceinline__ void ldsm_x4_t(uint32_t* r, uint32_t addr) {
    asm volatile("ldmatrix.sync.aligned.m8n8.x4.trans.shared.b16 {%0,%1,%2,%3}, [%4];"
                 : "=r"(r[0]), "=r"(r[1]), "=r"(r[2]), "=r"(r[3]) : "r"(addr));
}
__device__ __forceinline__ void mma16816(float* c, const uint32_t* a, uint32_t b0, uint32_t b1) {
    asm volatile(
        "mma.sync.aligned.m16n8k16.row.col.f32.bf16.bf16.f32 "
        "{%0,%1,%2,%3}, {%4,%5,%6,%7}, {%8,%9}, {%0,%1,%2,%3};"
        : "+f"(c[0]), "+f"(c[1]), "+f"(c[2]), "+f"(c[3])
        : "r"(a[0]), "r"(a[1]), "r"(a[2]), "r"(a[3]), "r"(b0), "r"(b1));
}

// bf16x3 chain step: B from smem (lo at +WLO_OFF), A frags in registers
#define CHAIN_STEP(acc, ah, al, bBase, ks) do { \
    uint32_t bRow = (bBase) + (uint32_t)(16 * (ks) + kofs) * 256; \
    _Pragma("unroll") \
    for (int jp = 0; jp < 8; jp++) { \
        uint32_t bh[4], bl[4]; \
        uint32_t baddr = bRow + (uint32_t)(((2 * jp + nsel) ^ l7) << 4); \
        ldsm_x4_t(bh, baddr); \
        ldsm_x4_t(bl, baddr + WLO_OFF); \
        mma16816(acc[2*jp],   ah, bh[0], bh[1]); \
        mma16816(acc[2*jp+1], ah, bh[2], bh[3]); \
        mma16816(acc[2*jp],   al, bh[0], bh[1]); \
        mma16816(acc[2*jp+1], al, bh[2], bh[3]); \
        mma16816(acc[2*jp],   ah, bl[0], bl[1]); \
        mma16816(acc[2*jp+1], ah, bl[2], bl[3]); \
    } \
} while (0)

// ---------------- scratch ----------------
__device__ float4 g_xa[N_NODES * DV];
__device__ float4 g_xb[N_NODES * DV];
__device__ uint2  g_hhi[N_NODES * 32];      // H hi (bf16 row-major, 4 vals/lane)
__device__ uint2  g_hlo[N_NODES * 32];
__device__ int    g_deg[N_NODES];
__device__ int    g_off[N_NODES + 1];
__device__ int    g_cur[N_NODES];
__device__ int    g_csr[N_EDGES];
__device__ int    g_bsums[64];
__device__ float  g_stats[NLAYERS * 2 * DD];
__device__ float4 g_pool[N_GRAPHS * DV];
__device__ float  g_cnt[N_GRAPHS];

// ---------------- CSR build ----------------
__global__ void k_deg(const int* __restrict__ ei) {
    int e = blockIdx.x * blockDim.x + threadIdx.x;
    if (e >= N_EDGES) return;
    unsigned d = (unsigned)ei[N_EDGES + e];
    if (d < N_NODES) atomicAdd(&g_deg[d], 1);
}
// hierarchical scan: block-local inclusive scans
__global__ void k_scan1() {
    __shared__ int sbuf[1024];
    int i = blockIdx.x * 1024 + threadIdx.x;
    int v = (i < N_NODES) ? g_deg[i] : 0;
    sbuf[threadIdx.x] = v;
    __syncthreads();
    for (int ofs = 1; ofs < 1024; ofs <<= 1) {
        int tv = (threadIdx.x >= ofs) ? sbuf[threadIdx.x - ofs] : 0;
        __syncthreads();
        sbuf[threadIdx.x] += tv;
        __syncthreads();
    }
    if (i < N_NODES) g_off[i + 1] = sbuf[threadIdx.x];
    if (threadIdx.x == 1023) g_bsums[blockIdx.x] = sbuf[1023];
}
__global__ void k_scan2() {   // 1 block, 64 threads: exclusive scan of block sums
    __shared__ int s[64];
    int v = (threadIdx.x < NSCAN) ? g_bsums[threadIdx.x] : 0;
    s[threadIdx.x] = v;
    __syncthreads();
    for (int ofs = 1; ofs < 64; ofs <<= 1) {
        int tv = (threadIdx.x >= ofs) ? s[threadIdx.x - ofs] : 0;
        __syncthreads();
        s[threadIdx.x] += tv;
        __syncthreads();
    }
    g_bsums[threadIdx.x] = (threadIdx.x == 0) ? 0 : s[threadIdx.x - 1];
}
__global__ void k_scan3() {
    int i = blockIdx.x * 1024 + threadIdx.x;
    if (i < N_NODES) g_off[i + 1] += g_bsums[blockIdx.x];
    if (i == 0) g_off[0] = 0;
}
__global__ void k_fill(const int* __restrict__ ei) {
    int e = blockIdx.x * blockDim.x + threadIdx.x;
    if (e >= N_EDGES) return;
    unsigned s = (unsigned)ei[e];
    unsigned d = (unsigned)ei[N_EDGES + e];
    if (s >= N_NODES || d >= N_NODES) return;
    int pos = atomicAdd(&g_cur[d], 1);
    g_csr[g_off[d] + pos] = (int)s;
}

// ---------------- gather: CSR walk + GIN combine + BN fold -> H hi/lo ----------------
__global__ void __launch_bounds__(256) k_gather(
    const float4* __restrict__ in,
    const float* __restrict__ stats_in,
    const float* __restrict__ gm, const float* __restrict__ bt,
    const float* __restrict__ epsp)
{
    const int lane = threadIdx.x & 31;
    const int gwarp = (blockIdx.x * blockDim.x + threadIdx.x) >> 5;
    const int nwarps = (gridDim.x * blockDim.x) >> 5;
    const float eps1 = 1.0f + epsp[0];

    float4 sc4 = make_float4(1.f, 1.f, 1.f, 1.f);
    float4 sh4 = make_float4(0.f, 0.f, 0.f, 0.f);
    if (stats_in) {
        const float invN = 1.0f / (float)N_NODES;
        int f = lane * 4;
        float* scp = reinterpret_cast<float*>(&sc4);
        float* shp = reinterpret_cast<float*>(&sh4);
        #pragma unroll
        for (int i = 0; i < 4; i++) {
            float mu = stats_in[f + i] * invN;
            float var = fmaf(stats_in[DD + f + i], invN, -mu * mu);
            float sc = gm[f + i] * rsqrtf(var + BN_EPS);
            scp[i] = sc;
            shp[i] = bt[f + i] - mu * sc;
        }
    }

    for (int node = gwarp; node < N_NODES; node += nwarps) {
        int beg = g_off[node], end = g_off[node + 1];
        float4 xv = in[node * DV + lane];
        float4 acc = make_float4(0.f, 0.f, 0.f, 0.f);
        int e = beg;
        for (; e + 4 <= end; e += 4) {
            int j0 = g_csr[e], j1 = g_csr[e+1], j2 = g_csr[e+2], j3 = g_csr[e+3];
            float4 v0 = in[j0 * DV + lane];
            float4 v1 = in[j1 * DV + lane];
            float4 v2 = in[j2 * DV + lane];
            float4 v3 = in[j3 * DV + lane];
            acc.x += (v0.x + v1.x) + (v2.x + v3.x);
            acc.y += (v0.y + v1.y) + (v2.y + v3.y);
            acc.z += (v0.z + v1.z) + (v2.z + v3.z);
            acc.w += (v0.w + v1.w) + (v2.w + v3.w);
        }
        for (; e < end; e++) {
            float4 v0 = in[g_csr[e] * DV + lane];
            acc.x += v0.x; acc.y += v0.y; acc.z += v0.z; acc.w += v0.w;
        }
        float f = eps1 + (float)(end - beg);
        float h0 = fmaf(sc4.x, fmaf(eps1, xv.x, acc.x), f * sh4.x);
        float h1 = fmaf(sc4.y, fmaf(eps1, xv.y, acc.y), f * sh4.y);
        float h2 = fmaf(sc4.z, fmaf(eps1, xv.z, acc.z), f * sh4.z);
        float h3 = fmaf(sc4.w, fmaf(eps1, xv.w, acc.w), f * sh4.w);
        g_hhi[node * 32 + lane] = make_uint2(pack_bf16x2(h0, h1), pack_bf16x2(h2, h3));
        g_hlo[node * 32 + lane] = make_uint2(
            pack_bf16x2(h0 - bf_round(h0), h1 - bf_round(h1)),
            pack_bf16x2(h2 - bf_round(h2), h3 - bf_round(h3)));
    }
}

// ---------------- fused GEMM: per-ks interleaved T conversion (low reg peak) ----------
extern __shared__ char gsm[];
__global__ void __launch_bounds__(32 * GWARPS, 1) k_gemm(
    float4* __restrict__ out,
    const float* __restrict__ W1, const float* __restrict__ b1,
    const float* __restrict__ W2, const float* __restrict__ b2,
    float* __restrict__ stats_out)
{
    const uint32_t sb = smem_u32(gsm);
    float* smemf = reinterpret_cast<float*>(gsm);
    const int t = threadIdx.x;
    const int lane = t & 31, wid = t >> 5;

    // stage W1 and W2 (hi/lo) into XOR-swizzled K-major smem
    for (int i4 = t; i4 < DD * 32; i4 += 32 * GWARPS) {
        int d = i4 >> 5, m = i4 & 31;
        float4 w1 = reinterpret_cast<const float4*>(W1)[i4];
        float4 w2 = reinterpret_cast<const float4*>(W2)[i4];
        uint32_t byte = (uint32_t)d * 256 + ((((uint32_t)(m >> 1)) ^ (d & 7)) << 4) + ((m & 1) << 3);
        *reinterpret_cast<uint2*>(gsm + OFF_W1 + byte) =
            make_uint2(pack_bf16x2(w1.x, w1.y), pack_bf16x2(w1.z, w1.w));
        *reinterpret_cast<uint2*>(gsm + OFF_W1 + WLO_OFF + byte) =
            make_uint2(pack_bf16x2(w1.x - bf_round(w1.x), w1.y - bf_round(w1.y)),
                       pack_bf16x2(w1.z - bf_round(w1.z), w1.w - bf_round(w1.w)));
        *reinterpret_cast<uint2*>(gsm + OFF_W2 + byte) =
            make_uint2(pack_bf16x2(w2.x, w2.y), pack_bf16x2(w2.z, w2.w));
        *reinterpret_cast<uint2*>(gsm + OFF_W2 + WLO_OFF + byte) =
            make_uint2(pack_bf16x2(w2.x - bf_round(w2.x), w2.y - bf_round(w2.y)),
                       pack_bf16x2(w2.z - bf_round(w2.z), w2.w - bf_round(w2.w)));
    }
    if (t < DD) { smemf[OFF_BS1/4 + t] = b1[t]; smemf[OFF_BS2/4 + t] = b2[t]; }
    if (t < 2 * DD) smemf[OFF_ST/4 + t] = 0.0f;
    __syncthreads();

    const int g = lane >> 2, tt = lane & 3;
    const int sel = lane >> 3;
    const int kofs = (lane & 7) + (sel & 1) * 8;
    const int nsel = sel >> 1;
    const int l7 = lane & 7;

    const uint32_t* hh = reinterpret_cast<const uint32_t*>(g_hhi);
    const uint32_t* hl = reinterpret_cast<const uint32_t*>(g_hlo);

    for (int blk = blockIdx.x * GWARPS + wid; blk < NBLK; blk += GRID_GEMM * GWARPS) {
        const int r0 = (blk * 16 + g) * 64;
        const int r1 = r0 + 8 * 64;

        // GEMM1: A loaded per-ks from global (ptxas front-batches within reg budget)
        float acc1[16][4];
        #pragma unroll
        for (int j = 0; j < 16; j++) { acc1[j][0]=0.f; acc1[j][1]=0.f; acc1[j][2]=0.f; acc1[j][3]=0.f; }
        #pragma unroll
        for (int ks = 0; ks < 8; ks++) {
            int p = ks * 8 + tt;
            uint32_t ah[4], al[4];
            ah[0] = hh[r0 + p];     ah[1] = hh[r1 + p];
            ah[2] = hh[r0 + p + 4]; ah[3] = hh[r1 + p + 4];
            al[0] = hl[r0 + p];     al[1] = hl[r1 + p];
            al[2] = hl[r0 + p + 4]; al[3] = hl[r1 + p + 4];
            CHAIN_STEP(acc1, ah, al, sb + OFF_W1, ks);
        }

        // GEMM2: convert acc1 chunk -> T frag per-ks, consume immediately
        float acc2[16][4];
        #pragma unroll
        for (int j = 0; j < 16; j++) { acc2[j][0]=0.f; acc2[j][1]=0.f; acc2[j][2]=0.f; acc2[j][3]=0.f; }
        #pragma unroll
        for (int ks = 0; ks < 8; ks++) {
            int j0 = 2 * ks, j1 = 2 * ks + 1;
            float b00 = smemf[OFF_BS1/4 + 16*ks + 2*tt],     b01 = smemf[OFF_BS1/4 + 16*ks + 2*tt + 1];
            float b10 = smemf[OFF_BS1/4 + 16*ks + 8 + 2*tt], b11 = smemf[OFF_BS1/4 + 16*ks + 8 + 2*tt + 1];
            float t0 = fmaxf(acc1[j0][0] + b00, 0.f), t1 = fmaxf(acc1[j0][1] + b01, 0.f);
            float t2 = fmaxf(acc1[j0][2] + b00, 0.f), t3 = fmaxf(acc1[j0][3] + b01, 0.f);
            float t4 = fmaxf(acc1[j1][0] + b10, 0.f), t5 = fmaxf(acc1[j1][1] + b11, 0.f);
            float t6 = fmaxf(acc1[j1][2] + b10, 0.f), t7 = fmaxf(acc1[j1][3] + b11, 0.f);
            uint32_t th[4], tl[4];
            th[0] = pack_bf16x2(t0, t1); th[1] = pack_bf16x2(t2, t3);
            th[2] = pack_bf16x2(t4, t5); th[3] = pack_bf16x2(t6, t7);
            tl[0] = pack_bf16x2(t0 - bf_round(t0), t1 - bf_round(t1));
            tl[1] = pack_bf16x2(t2 - bf_round(t2), t3 - bf_round(t3));
            tl[2] = pack_bf16x2(t4 - bf_round(t4), t5 - bf_round(t5));
            tl[3] = pack_bf16x2(t6 - bf_round(t6), t7 - bf_round(t7));
            CHAIN_STEP(acc2, th, tl, sb + OFF_W2, ks);
        }

        // epilogue: y = relu(acc2 + b2); store row-major; BN stats (smem-staged)
        {
            int node0 = blk * 16 + g;
            int node1 = node0 + 8;
            float2* outv2 = reinterpret_cast<float2*>(out);
            #pragma unroll
            for (int j = 0; j < 16; j++) {
                int n0 = 8 * j + 2 * tt;
                float be0 = smemf[OFF_BS2/4 + n0], be1 = smemf[OFF_BS2/4 + n0 + 1];
                float y0 = fmaxf(acc2[j][0] + be0, 0.f);
                float y1 = fmaxf(acc2[j][1] + be1, 0.f);
                float y2 = fmaxf(acc2[j][2] + be0, 0.f);
                float y3 = fmaxf(acc2[j][3] + be1, 0.f);
                outv2[node0 * 64 + 4 * j + tt] = make_float2(y0, y1);
                outv2[node1 * 64 + 4 * j + tt] = make_float2(y2, y3);
                float se = y0 + y2, so = y1 + y3;
                float qe = y0*y0 + y2*y2, qo = y1*y1 + y3*y3;
                #pragma unroll
                for (int off = 4; off < 32; off <<= 1) {
                    se += __shfl_xor_sync(0xFFFFFFFFu, se, off);
                    so += __shfl_xor_sync(0xFFFFFFFFu, so, off);
                    qe += __shfl_xor_sync(0xFFFFFFFFu, qe, off);
                    qo += __shfl_xor_sync(0xFFFFFFFFu, qo, off);
                }
                if (g == 0) {
                    atomicAdd(&smemf[OFF_ST/4 + n0],           se);
                    atomicAdd(&smemf[OFF_ST/4 + n0 + 1],       so);
                    atomicAdd(&smemf[OFF_ST/4 + 128 + n0],     qe);
                    atomicAdd(&smemf[OFF_ST/4 + 128 + n0 + 1], qo);
                }
            }
        }
    }

    __syncthreads();
    if (t < 2 * DD) atomicAdd(&stats_out[t], smemf[OFF_ST/4 + t]);
}

// ---------------- pool + head ----------------
__global__ void k_pool(const int* __restrict__ batch, const float4* __restrict__ in) {
    int idx = blockIdx.x * blockDim.x + threadIdx.x;
    int n = idx >> 5;
    int k = idx & 31;
    if (n >= N_NODES) return;
    unsigned g = (unsigned)batch[n];
    if (g >= N_GRAPHS) return;
    float4 v = in[n * DV + k];
    atomicAdd(&g_pool[g * DV + k], v);
    if (k == 0) atomicAdd(&g_cnt[g], 1.0f);
}

__global__ void k_final(const float* __restrict__ We, const float* __restrict__ be,
                        const float* __restrict__ gm, const float* __restrict__ bt,
                        float* __restrict__ out) {
    __shared__ float sp[DD];
    int b = blockIdx.x;
    int o = threadIdx.x;
    const float invN = 1.0f / (float)N_NODES;
    const float* st = g_stats + (NLAYERS - 1) * 2 * DD;
    float mu = st[o] * invN;
    float var = fmaf(st[DD + o], invN, -mu * mu);
    float sc = gm[o] * rsqrtf(var + BN_EPS);
    float sh = bt[o] - mu * sc;
    float c = fmaxf(g_cnt[b], 1.0f);
    float sum = reinterpret_cast<const float*>(g_pool)[b * DD + o];
    sp[o] = fmaf(sc, sum / c, sh);
    __syncthreads();
    float accv = be[o];
    #pragma unroll 4
    for (int d = 0; d < DD; d++) accv = fmaf(sp[d], We[d * DD + o], accv);
    out[b * DD + o] = accv;
}

extern "C" void kernel_launch(void* const* d_in, const int* in_sizes, int n_in,
                              void* d_out, int out_size) {
    const float* x     = (const float*)d_in[0];
    const int*   ei    = (const int*)d_in[1];
    const int*   batch = (const int*)d_in[2];
    const float* W1    = (const float*)d_in[3];
    const float* b1    = (const float*)d_in[4];
    const float* W2    = (const float*)d_in[5];
    const float* b2    = (const float*)d_in[6];
    const float* eps   = (const float*)d_in[7];
    const float* gamma = (const float*)d_in[8];
    const float* beta  = (const float*)d_in[9];
    const float* We    = (const float*)d_in[10];
    const float* be    = (const float*)d_in[11];
    float* out = (float*)d_out;

    void *p_xa, *p_xb, *p_deg, *p_cur, *p_stats, *p_pool, *p_cnt;
    cudaGetSymbolAddress(&p_xa, g_xa);
    cudaGetSymbolAddress(&p_xb, g_xb);
    cudaGetSymbolAddress(&p_deg, g_deg);
    cudaGetSymbolAddress(&p_cur, g_cur);
    cudaGetSymbolAddress(&p_stats, g_stats);
    cudaGetSymbolAddress(&p_pool, g_pool);
    cudaGetSymbolAddress(&p_cnt, g_cnt);
    float* stats = (float*)p_stats;

    cudaFuncSetAttribute(k_gemm, cudaFuncAttributeMaxDynamicSharedMemorySize, SMEM_G);

    cudaMemsetAsync(p_deg, 0, N_NODES * sizeof(int), 0);
    cudaMemsetAsync(p_cur, 0, N_NODES * sizeof(int), 0);
    cudaMemsetAsync(p_stats, 0, NLAYERS * 2 * DD * sizeof(float), 0);
    const int eb = (N_EDGES + 255) / 256;
    k_deg<<<eb, 256>>>(ei);
    k_scan1<<<NSCAN, 1024>>>();
    k_scan2<<<1, 64>>>();
    k_scan3<<<NSCAN, 1024>>>();
    k_fill<<<eb, 256>>>(ei);

    const float4* bufs_in[3]  = { (const float4*)x, (const float4*)p_xa, (const float4*)p_xb };
    float4*       bufs_out[3] = { (float4*)p_xa, (float4*)p_xb, (float4*)p_xa };
    for (int l = 0; l < NLAYERS; l++) {
        const float* st_in = (l == 0) ? nullptr : stats + (l - 1) * 2 * DD;
        const float* gm = (l == 0) ? gamma : gamma + (l - 1) * DD;
        const float* bt = (l == 0) ? beta  : beta  + (l - 1) * DD;
        k_gather<<<1184, 256>>>(bufs_in[l], st_in, gm, bt, eps + l);
        k_gemm<<<GRID_GEMM, 32 * GWARPS, SMEM_G>>>(bufs_out[l],
                                                   W1 + l*DD*DD, b1 + l*DD,
                                                   W2 + l*DD*DD, b2 + l*DD,
                                                   stats + l * 2 * DD);
    }

    cudaMemsetAsync(p_pool, 0, (size_t)N_GRAPHS * DD * sizeof(float), 0);
    cudaMemsetAsync(p_cnt, 0, N_GRAPHS * sizeof(float), 0);
    const int pool_blocks = (N_NODES * 32 + 255) / 256;
    k_pool<<<pool_blocks, 256>>>(batch, bufs_out[NLAYERS - 1]);
    k_final<<<N_GRAPHS, DD>>>(We, be, gamma + (NLAYERS-1)*DD, beta + (NLAYERS-1)*DD, out);
}

// round 16
// speedup vs baseline: 1.4704x; 1.0589x over previous
#include <cuda_runtime.h>
#include <cuda_bf16.h>
#include <cstdint>

#define N_NODES 50000
#define N_EDGES 800000
#define N_GRAPHS 256
#define DD 128
#define DV 32
#define NLAYERS 3
#define NBLK 3125                 // 16-row blocks (50000 = 3125*16 exactly)
#define GRID_GEMM 148
#define GWARPS 12                 // warps per gemm CTA
#define BN_EPS 1e-5f
#define NSCAN 49                  // ceil(50000/1024)

// ---- k_gemm smem layout (bytes): W1 hi|lo, W2 hi|lo, b1, b2, stats ----
#define WLO_OFF  32768
#define OFF_W1   0
#define OFF_W2   65536
#define OFF_BS1  131072
#define OFF_BS2  131584
#define OFF_ST   132096
#define SMEM_G   133120

__device__ __forceinline__ uint32_t smem_u32(const void* p) {
    uint32_t a;
    asm("{ .reg .u64 t; cvta.to.shared.u64 t, %1; cvt.u32.u64 %0, t; }" : "=r"(a) : "l"(p));
    return a;
}
__device__ __forceinline__ uint32_t pack_bf16x2(float a, float b) {
    uint32_t r;
    asm("cvt.rn.bf16x2.f32 %0, %1, %2;" : "=r"(r) : "f"(b), "f"(a));
    return r;
}
__device__ __forceinline__ float bf_round(float v) {
    return __bfloat162float(__float2bfloat16(v));
}
__device__ __forceinline__ void ldsm_x4_t(uint32_t* r, uint32_t addr) {
    asm volatile("ldmatrix.sync.aligned.m8n8.x4.trans.shared.b16 {%0,%1,%2,%3}, [%4];"
                 : "=r"(r[0]), "=r"(r[1]), "=r"(r[2]), "=r"(r[3]) : "r"(addr));
}
__device__ __forceinline__ void mma16816(float* c, const uint32_t* a, uint32_t b0, uint32_t b1) {
    asm volatile(
        "mma.sync.aligned.m16n8k16.row.col.f32.bf16.bf16.f32 "
        "{%0,%1,%2,%3}, {%4,%5,%6,%7}, {%8,%9}, {%0,%1,%2,%3};"
        : "+f"(c[0]), "+f"(c[1]), "+f"(c[2]), "+f"(c[3])
        : "r"(a[0]), "r"(a[1]), "r"(a[2]), "r"(a[3]), "r"(b0), "r"(b1));
}

// bf16x3 chain step: B from smem (lo at +WLO_OFF), A frags in registers
#define CHAIN_STEP(acc, ah, al, bBase, ks) do { \
    uint32_t bRow = (bBase) + (uint32_t)(16 * (ks) + kofs) * 256; \
    _Pragma("unroll") \
    for (int jp = 0; jp < 8; jp++) { \
        uint32_t bh[4], bl[4]; \
        uint32_t baddr = bRow + (uint32_t)(((2 * jp + nsel) ^ l7) << 4); \
        ldsm_x4_t(bh, baddr); \
        ldsm_x4_t(bl, baddr + WLO_OFF); \
        mma16816(acc[2*jp],   ah, bh[0], bh[1]); \
        mma16816(acc[2*jp+1], ah, bh[2], bh[3]); \
        mma16816(acc[2*jp],   al, bh[0], bh[1]); \
        mma16816(acc[2*jp+1], al, bh[2], bh[3]); \
        mma16816(acc[2*jp],   ah, bl[0], bl[1]); \
        mma16816(acc[2*jp+1], ah, bl[2], bl[3]); \
    } \
} while (0)

// ---------------- scratch ----------------
__device__ float4 g_xa[N_NODES * DV];
__device__ float4 g_xb[N_NODES * DV];
__device__ uint2  g_hhi[N_NODES * 32];      // H hi (bf16 row-major, 4 vals/lane)
__device__ uint2  g_hlo[N_NODES * 32];
__device__ int    g_deg[N_NODES];
__device__ int    g_off[N_NODES + 1];
__device__ int    g_cur[N_NODES];
__device__ int    g_csr[N_EDGES];
__device__ int    g_bsums[64];
__device__ float  g_stats[NLAYERS * 2 * DD];
__device__ float4 g_pool[N_GRAPHS * DV];
__device__ float  g_cnt[N_GRAPHS];

// ---------------- CSR build ----------------
__global__ void k_deg(const int* __restrict__ ei) {
    int e = blockIdx.x * blockDim.x + threadIdx.x;
    if (e >= N_EDGES) return;
    unsigned d = (unsigned)ei[N_EDGES + e];
    if (d < N_NODES) atomicAdd(&g_deg[d], 1);
}
__global__ void k_scan1() {
    __shared__ int sbuf[1024];
    int i = blockIdx.x * 1024 + threadIdx.x;
    int v = (i < N_NODES) ? g_deg[i] : 0;
    sbuf[threadIdx.x] = v;
    __syncthreads();
    for (int ofs = 1; ofs < 1024; ofs <<= 1) {
        int tv = (threadIdx.x >= ofs) ? sbuf[threadIdx.x - ofs] : 0;
        __syncthreads();
        sbuf[threadIdx.x] += tv;
        __syncthreads();
    }
    if (i < N_NODES) g_off[i + 1] = sbuf[threadIdx.x];
    if (threadIdx.x == 1023) g_bsums[blockIdx.x] = sbuf[1023];
}
__global__ void k_scan2() {
    __shared__ int s[64];
    int v = (threadIdx.x < NSCAN) ? g_bsums[threadIdx.x] : 0;
    s[threadIdx.x] = v;
    __syncthreads();
    for (int ofs = 1; ofs < 64; ofs <<= 1) {
        int tv = (threadIdx.x >= ofs) ? s[threadIdx.x - ofs] : 0;
        __syncthreads();
        s[threadIdx.x] += tv;
        __syncthreads();
    }
    g_bsums[threadIdx.x] = (threadIdx.x == 0) ? 0 : s[threadIdx.x - 1];
}
__global__ void k_scan3() {
    int i = blockIdx.x * 1024 + threadIdx.x;
    if (i < N_NODES) g_off[i + 1] += g_bsums[blockIdx.x];
    if (i == 0) g_off[0] = 0;
}
__global__ void k_fill(const int* __restrict__ ei) {
    int e = blockIdx.x * blockDim.x + threadIdx.x;
    if (e >= N_EDGES) return;
    unsigned s = (unsigned)ei[e];
    unsigned d = (unsigned)ei[N_EDGES + e];
    if (s >= N_NODES || d >= N_NODES) return;
    int pos = atomicAdd(&g_cur[d], 1);
    g_csr[g_off[d] + pos] = (int)s;
}

// ---------------- gather: CSR walk + GIN combine + BN fold -> H hi/lo ----------------
// launch_bounds(256, 8): cap regs at 32 for full 2048-thread occupancy (L2 MLP)
__global__ void __launch_bounds__(256, 8) k_gather(
    const float4* __restrict__ in,
    const float* __restrict__ stats_in,
    const float* __restrict__ gm, const float* __restrict__ bt,
    const float* __restrict__ epsp)
{
    const int lane = threadIdx.x & 31;
    const int gwarp = (blockIdx.x * blockDim.x + threadIdx.x) >> 5;
    const int nwarps = (gridDim.x * blockDim.x) >> 5;
    const float eps1 = 1.0f + epsp[0];

    float4 sc4 = make_float4(1.f, 1.f, 1.f, 1.f);
    float4 sh4 = make_float4(0.f, 0.f, 0.f, 0.f);
    if (stats_in) {
        const float invN = 1.0f / (float)N_NODES;
        int f = lane * 4;
        float* scp = reinterpret_cast<float*>(&sc4);
        float* shp = reinterpret_cast<float*>(&sh4);
        #pragma unroll
        for (int i = 0; i < 4; i++) {
            float mu = stats_in[f + i] * invN;
            float var = fmaf(stats_in[DD + f + i], invN, -mu * mu);
            float sc = gm[f + i] * rsqrtf(var + BN_EPS);
            scp[i] = sc;
            shp[i] = bt[f + i] - mu * sc;
        }
    }

    for (int node = gwarp; node < N_NODES; node += nwarps) {
        int beg = g_off[node], end = g_off[node + 1];
        float4 xv = in[node * DV + lane];
        float4 acc = make_float4(0.f, 0.f, 0.f, 0.f);
        int e = beg;
        for (; e + 4 <= end; e += 4) {
            int j0 = g_csr[e], j1 = g_csr[e+1], j2 = g_csr[e+2], j3 = g_csr[e+3];
            float4 v0 = in[j0 * DV + lane];
            float4 v1 = in[j1 * DV + lane];
            float4 v2 = in[j2 * DV + lane];
            float4 v3 = in[j3 * DV + lane];
            acc.x += (v0.x + v1.x) + (v2.x + v3.x);
            acc.y += (v0.y + v1.y) + (v2.y + v3.y);
            acc.z += (v0.z + v1.z) + (v2.z + v3.z);
            acc.w += (v0.w + v1.w) + (v2.w + v3.w);
        }
        for (; e < end; e++) {
            float4 v0 = in[g_csr[e] * DV + lane];
            acc.x += v0.x; acc.y += v0.y; acc.z += v0.z; acc.w += v0.w;
        }
        float f = eps1 + (float)(end - beg);
        float h0 = fmaf(sc4.x, fmaf(eps1, xv.x, acc.x), f * sh4.x);
        float h1 = fmaf(sc4.y, fmaf(eps1, xv.y, acc.y), f * sh4.y);
        float h2 = fmaf(sc4.z, fmaf(eps1, xv.z, acc.z), f * sh4.z);
        float h3 = fmaf(sc4.w, fmaf(eps1, xv.w, acc.w), f * sh4.w);
        g_hhi[node * 32 + lane] = make_uint2(pack_bf16x2(h0, h1), pack_bf16x2(h2, h3));
        g_hlo[node * 32 + lane] = make_uint2(
            pack_bf16x2(h0 - bf_round(h0), h1 - bf_round(h1)),
            pack_bf16x2(h2 - bf_round(h2), h3 - bf_round(h3)));
    }
}

// ---------------- fused GEMM: per-ks interleaved T conversion (low reg peak) ----------
extern __shared__ char gsm[];
__global__ void __launch_bounds__(32 * GWARPS, 1) k_gemm(
    float4* __restrict__ out,
    const float* __restrict__ W1, const float* __restrict__ b1,
    const float* __restrict__ W2, const float* __restrict__ b2,
    float* __restrict__ stats_out)
{
    const uint32_t sb = smem_u32(gsm);
    float* smemf = reinterpret_cast<float*>(gsm);
    const int t = threadIdx.x;
    const int lane = t & 31, wid = t >> 5;

    // stage W1 and W2 (hi/lo) into XOR-swizzled K-major smem
    for (int i4 = t; i4 < DD * 32; i4 += 32 * GWARPS) {
        int d = i4 >> 5, m = i4 & 31;
        float4 w1 = reinterpret_cast<const float4*>(W1)[i4];
        float4 w2 = reinterpret_cast<const float4*>(W2)[i4];
        uint32_t byte = (uint32_t)d * 256 + ((((uint32_t)(m >> 1)) ^ (d & 7)) << 4) + ((m & 1) << 3);
        *reinterpret_cast<uint2*>(gsm + OFF_W1 + byte) =
            make_uint2(pack_bf16x2(w1.x, w1.y), pack_bf16x2(w1.z, w1.w));
        *reinterpret_cast<uint2*>(gsm + OFF_W1 + WLO_OFF + byte) =
            make_uint2(pack_bf16x2(w1.x - bf_round(w1.x), w1.y - bf_round(w1.y)),
                       pack_bf16x2(w1.z - bf_round(w1.z), w1.w - bf_round(w1.w)));
        *reinterpret_cast<uint2*>(gsm + OFF_W2 + byte) =
            make_uint2(pack_bf16x2(w2.x, w2.y), pack_bf16x2(w2.z, w2.w));
        *reinterpret_cast<uint2*>(gsm + OFF_W2 + WLO_OFF + byte) =
            make_uint2(pack_bf16x2(w2.x - bf_round(w2.x), w2.y - bf_round(w2.y)),
                       pack_bf16x2(w2.z - bf_round(w2.z), w2.w - bf_round(w2.w)));
    }
    if (t < DD) { smemf[OFF_BS1/4 + t] = b1[t]; smemf[OFF_BS2/4 + t] = b2[t]; }
    if (t < 2 * DD) smemf[OFF_ST/4 + t] = 0.0f;
    __syncthreads();

    const int g = lane >> 2, tt = lane & 3;
    const int sel = lane >> 3;
    const int kofs = (lane & 7) + (sel & 1) * 8;
    const int nsel = sel >> 1;
    const int l7 = lane & 7;

    const uint32_t* hh = reinterpret_cast<const uint32_t*>(g_hhi);
    const uint32_t* hl = reinterpret_cast<const uint32_t*>(g_hlo);

    for (int blk = blockIdx.x * GWARPS + wid; blk < NBLK; blk += GRID_GEMM * GWARPS) {
        const int r0 = (blk * 16 + g) * 64;
        const int r1 = r0 + 8 * 64;

        // GEMM1: A loaded per-ks from global (ptxas front-batches within reg budget)
        float acc1[16][4];
        #pragma unroll
        for (int j = 0; j < 16; j++) { acc1[j][0]=0.f; acc1[j][1]=0.f; acc1[j][2]=0.f; acc1[j][3]=0.f; }
        #pragma unroll
        for (int ks = 0; ks < 8; ks++) {
            int p = ks * 8 + tt;
            uint32_t ah[4], al[4];
            ah[0] = hh[r0 + p];     ah[1] = hh[r1 + p];
            ah[2] = hh[r0 + p + 4]; ah[3] = hh[r1 + p + 4];
            al[0] = hl[r0 + p];     al[1] = hl[r1 + p];
            al[2] = hl[r0 + p + 4]; al[3] = hl[r1 + p + 4];
            CHAIN_STEP(acc1, ah, al, sb + OFF_W1, ks);
        }

        // GEMM2: convert acc1 chunk -> T frag per-ks, consume immediately
        float acc2[16][4];
        #pragma unroll
        for (int j = 0; j < 16; j++) { acc2[j][0]=0.f; acc2[j][1]=0.f; acc2[j][2]=0.f; acc2[j][3]=0.f; }
        #pragma unroll
        for (int ks = 0; ks < 8; ks++) {
            int j0 = 2 * ks, j1 = 2 * ks + 1;
            float b00 = smemf[OFF_BS1/4 + 16*ks + 2*tt],     b01 = smemf[OFF_BS1/4 + 16*ks + 2*tt + 1];
            float b10 = smemf[OFF_BS1/4 + 16*ks + 8 + 2*tt], b11 = smemf[OFF_BS1/4 + 16*ks + 8 + 2*tt + 1];
            float t0 = fmaxf(acc1[j0][0] + b00, 0.f), t1 = fmaxf(acc1[j0][1] + b01, 0.f);
            float t2 = fmaxf(acc1[j0][2] + b00, 0.f), t3 = fmaxf(acc1[j0][3] + b01, 0.f);
            float t4 = fmaxf(acc1[j1][0] + b10, 0.f), t5 = fmaxf(acc1[j1][1] + b11, 0.f);
            float t6 = fmaxf(acc1[j1][2] + b10, 0.f), t7 = fmaxf(acc1[j1][3] + b11, 0.f);
            uint32_t th[4], tl[4];
            th[0] = pack_bf16x2(t0, t1); th[1] = pack_bf16x2(t2, t3);
            th[2] = pack_bf16x2(t4, t5); th[3] = pack_bf16x2(t6, t7);
            tl[0] = pack_bf16x2(t0 - bf_round(t0), t1 - bf_round(t1));
            tl[1] = pack_bf16x2(t2 - bf_round(t2), t3 - bf_round(t3));
            tl[2] = pack_bf16x2(t4 - bf_round(t4), t5 - bf_round(t5));
            tl[3] = pack_bf16x2(t6 - bf_round(t6), t7 - bf_round(t7));
            CHAIN_STEP(acc2, th, tl, sb + OFF_W2, ks);
        }

        // epilogue: y = relu(acc2 + b2); store row-major; BN stats (smem-staged)
        {
            int node0 = blk * 16 + g;
            int node1 = node0 + 8;
            float2* outv2 = reinterpret_cast<float2*>(out);
            #pragma unroll
            for (int j = 0; j < 16; j++) {
                int n0 = 8 * j + 2 * tt;
                float be0 = smemf[OFF_BS2/4 + n0], be1 = smemf[OFF_BS2/4 + n0 + 1];
                float y0 = fmaxf(acc2[j][0] + be0, 0.f);
                float y1 = fmaxf(acc2[j][1] + be1, 0.f);
                float y2 = fmaxf(acc2[j][2] + be0, 0.f);
                float y3 = fmaxf(acc2[j][3] + be1, 0.f);
                outv2[node0 * 64 + 4 * j + tt] = make_float2(y0, y1);
                outv2[node1 * 64 + 4 * j + tt] = make_float2(y2, y3);
                float se = y0 + y2, so = y1 + y3;
                float qe = y0*y0 + y2*y2, qo = y1*y1 + y3*y3;
                #pragma unroll
                for (int off = 4; off < 32; off <<= 1) {
                    se += __shfl_xor_sync(0xFFFFFFFFu, se, off);
                    so += __shfl_xor_sync(0xFFFFFFFFu, so, off);
                    qe += __shfl_xor_sync(0xFFFFFFFFu, qe, off);
                    qo += __shfl_xor_sync(0xFFFFFFFFu, qo, off);
                }
                if (g == 0) {
                    atomicAdd(&smemf[OFF_ST/4 + n0],           se);
                    atomicAdd(&smemf[OFF_ST/4 + n0 + 1],       so);
                    atomicAdd(&smemf[OFF_ST/4 + 128 + n0],     qe);
                    atomicAdd(&smemf[OFF_ST/4 + 128 + n0 + 1], qo);
                }
            }
        }
    }

    __syncthreads();
    if (t < 2 * DD) atomicAdd(&stats_out[t], smemf[OFF_ST/4 + t]);
}

// ---------------- pool: segmented (batch sorted) — 8 nodes per warp-lane pass --------
__global__ void __launch_bounds__(256) k_pool(const int* __restrict__ batch,
                                              const float4* __restrict__ in) {
    const int lane = threadIdx.x & 31;
    const int w = (blockIdx.x * blockDim.x + threadIdx.x) >> 5;   // warp id
    int n0 = w * 8;
    if (n0 >= N_NODES) return;
    int n1 = min(n0 + 8, N_NODES);
    float4 acc = make_float4(0.f, 0.f, 0.f, 0.f);
    int cur = batch[n0];
    int runlen = 0;
    for (int n = n0; n < n1; n++) {
        int g = batch[n];
        if (g != cur) {
            if ((unsigned)cur < N_GRAPHS) {
                atomicAdd(&g_pool[cur * DV + lane], acc);
                if (lane == 0) atomicAdd(&g_cnt[cur], (float)runlen);
            }
            acc = make_float4(0.f, 0.f, 0.f, 0.f);
            cur = g; runlen = 0;
        }
        float4 v = in[n * DV + lane];
        acc.x += v.x; acc.y += v.y; acc.z += v.z; acc.w += v.w;
        runlen++;
    }
    if ((unsigned)cur < N_GRAPHS) {
        atomicAdd(&g_pool[cur * DV + lane], acc);
        if (lane == 0) atomicAdd(&g_cnt[cur], (float)runlen);
    }
}

__global__ void k_final(const float* __restrict__ We, const float* __restrict__ be,
                        const float* __restrict__ gm, const float* __restrict__ bt,
                        float* __restrict__ out) {
    __shared__ float sp[DD];
    int b = blockIdx.x;
    int o = threadIdx.x;
    const float invN = 1.0f / (float)N_NODES;
    const float* st = g_stats + (NLAYERS - 1) * 2 * DD;
    float mu = st[o] * invN;
    float var = fmaf(st[DD + o], invN, -mu * mu);
    float sc = gm[o] * rsqrtf(var + BN_EPS);
    float sh = bt[o] - mu * sc;
    float c = fmaxf(g_cnt[b], 1.0f);
    float sum = reinterpret_cast<const float*>(g_pool)[b * DD + o];
    sp[o] = fmaf(sc, sum / c, sh);
    __syncthreads();
    float accv = be[o];
    #pragma unroll 4
    for (int d = 0; d < DD; d++) accv = fmaf(sp[d], We[d * DD + o], accv);
    out[b * DD + o] = accv;
}

extern "C" void kernel_launch(void* const* d_in, const int* in_sizes, int n_in,
                              void* d_out, int out_size) {
    const float* x     = (const float*)d_in[0];
    const int*   ei    = (const int*)d_in[1];
    const int*   batch = (const int*)d_in[2];
    const float* W1    = (const float*)d_in[3];
    const float* b1    = (const float*)d_in[4];
    const float* W2    = (const float*)d_in[5];
    const float* b2    = (const float*)d_in[6];
    const float* eps   = (const float*)d_in[7];
    const float* gamma = (const float*)d_in[8];
    const float* beta  = (const float*)d_in[9];
    const float* We    = (const float*)d_in[10];
    const float* be    = (const float*)d_in[11];
    float* out = (float*)d_out;

    void *p_xa, *p_xb, *p_deg, *p_cur, *p_stats, *p_pool, *p_cnt;
    cudaGetSymbolAddress(&p_xa, g_xa);
    cudaGetSymbolAddress(&p_xb, g_xb);
    cudaGetSymbolAddress(&p_deg, g_deg);
    cudaGetSymbolAddress(&p_cur, g_cur);
    cudaGetSymbolAddress(&p_stats, g_stats);
    cudaGetSymbolAddress(&p_pool, g_pool);
    cudaGetSymbolAddress(&p_cnt, g_cnt);
    float* stats = (float*)p_stats;

    cudaFuncSetAttribute(k_gemm, cudaFuncAttributeMaxDynamicSharedMemorySize, SMEM_G);

    cudaMemsetAsync(p_deg, 0, N_NODES * sizeof(int), 0);
    cudaMemsetAsync(p_cur, 0, N_NODES * sizeof(int), 0);
    cudaMemsetAsync(p_stats, 0, NLAYERS * 2 * DD * sizeof(float), 0);
    const int eb = (N_EDGES + 255) / 256;
    k_deg<<<eb, 256>>>(ei);
    k_scan1<<<NSCAN, 1024>>>();
    k_scan2<<<1, 64>>>();
    k_scan3<<<NSCAN, 1024>>>();
    k_fill<<<eb, 256>>>(ei);

    const float4* bufs_in[3]  = { (const float4*)x, (const float4*)p_xa, (const float4*)p_xb };
    float4*       bufs_out[3] = { (float4*)p_xa, (float4*)p_xb, (float4*)p_xa };
    for (int l = 0; l < NLAYERS; l++) {
        const float* st_in = (l == 0) ? nullptr : stats + (l - 1) * 2 * DD;
        const float* gm = (l == 0) ? gamma : gamma + (l - 1) * DD;
        const float* bt = (l == 0) ? beta  : beta  + (l - 1) * DD;
        k_gather<<<1184, 256>>>(bufs_in[l], st_in, gm, bt, eps + l);
        k_gemm<<<GRID_GEMM, 32 * GWARPS, SMEM_G>>>(bufs_out[l],
                                                   W1 + l*DD*DD, b1 + l*DD,
                                                   W2 + l*DD*DD, b2 + l*DD,
                                                   stats + l * 2 * DD);
    }

    cudaMemsetAsync(p_pool, 0, (size_t)N_GRAPHS * DD * sizeof(float), 0);
    cudaMemsetAsync(p_cnt, 0, N_GRAPHS * sizeof(float), 0);
    const int pool_blocks = ((N_NODES + 7) / 8 * 32 + 255) / 256;
    k_pool<<<pool_blocks, 256>>>(batch, bufs_out[NLAYERS - 1]);
    k_final<<<N_GRAPHS, DD>>>(We, be, gamma + (NLAYERS-1)*DD, beta + (NLAYERS-1)*DD, out);
}